// round 13
// baseline (speedup 1.0000x reference)
#include <cuda_runtime.h>
#include <stdint.h>

#define BATCH 32
#define HW    196        // 14x14
#define CIN   1024
#define CMID  256
#define COUT  1024
#define NCB1  256        // 1024/4
#define NCB2  256        // one codebook per channel (dsub=9)
#define NCB3  64         // 256/4
#define KC    16

// Scratch (no runtime allocation allowed)
__device__ float g_out1[BATCH * CMID * HW];
__device__ float g_out2[BATCH * CMID * HW];

__device__ __forceinline__ float smul(float a, float b) { return __fmul_rn(a, b); }
__device__ __forceinline__ float sadd(float a, float b) { return __fadd_rn(a, b); }
__device__ __forceinline__ float ssub(float a, float b) { return __fsub_rn(a, b); }

// Kahan step: acc += t with compensation
#define KAHAN(s, comp, t) do {                         \
    float _y  = ssub((t), (comp));                     \
    float _tt = sadd((s), _y);                         \
    (comp) = ssub(ssub(_tt, (s)), _y);                 \
    (s) = _tt;                                         \
} while (0)

// ---------------------------------------------------------------------------
// fp64 argmin fallback for near-ties (matches the fp64 reference exactly)
// ---------------------------------------------------------------------------
__device__ __noinline__ int argmin_d4(const float* __restrict__ c,
                                      float v0, float v1, float v2, float v3)
{
    double bv = 1e300; int bk = 0;
    for (int k = 0; k < KC; k++) {
        const float* ck = c + k * 4;
        double c2 = (double)ck[0]*ck[0] + (double)ck[1]*ck[1]
                  + (double)ck[2]*ck[2] + (double)ck[3]*ck[3];
        double dot = (double)ck[0]*v0 + (double)ck[1]*v1
                   + (double)ck[2]*v2 + (double)ck[3]*v3;
        double s = c2 - 2.0 * dot;
        if (s < bv) { bv = s; bk = k; }
    }
    return bk;
}

__device__ __noinline__ int argmin_d9(const float* __restrict__ c,
                                      const float* __restrict__ v)
{
    double bv = 1e300; int bk = 0;
    for (int k = 0; k < KC; k++) {
        const float* ck = c + k * 9;
        double c2 = 0.0, dot = 0.0;
        for (int d = 0; d < 9; d++) {
            c2  += (double)ck[d] * ck[d];
            dot += (double)ck[d] * v[d];
        }
        double s = c2 - 2.0 * dot;
        if (s < bv) { bv = s; bk = k; }
    }
    return bk;
}

// ---------------------------------------------------------------------------
// Kernel 1: 1x1 AMM conv  (x[32,1024,14,14] -> out1[32,256,14,14]) + BN + ReLU
// grid (7, 32): 28 positions per block. 512 threads.
// ---------------------------------------------------------------------------
__global__ __launch_bounds__(512, 2) void k1_assign_accum(
    const float* __restrict__ x, const float* __restrict__ cent,
    const float* __restrict__ lut, const float* __restrict__ scale,
    const float* __restrict__ bias)
{
    __shared__ float         s_c2[NCB1 * KC];      // 16 KB
    __shared__ unsigned char s_idx[NCB1 * 28];     // [cb][p]

    const int b   = blockIdx.y;
    const int pt  = blockIdx.x;
    const int tid = threadIdx.x;

    for (int i = tid; i < NCB1 * KC; i += 512) {
        const float* c = cent + i * 4;
        float s = 0.f;
        #pragma unroll
        for (int d = 0; d < 4; d++) s = sadd(s, smul(c[d], c[d]));
        s_c2[i] = s;
    }
    __syncthreads();

    const float* xb = x + (size_t)b * CIN * HW;
    for (int pr = tid; pr < NCB1 * 28; pr += 512) {
        const int cb = pr / 28;
        const int p  = pr - cb * 28;
        const int pg = pt * 28 + p;
        const float* xv = xb + (cb * 4) * HW + pg;
        const float v0 = xv[0], v1 = xv[HW], v2 = xv[2*HW], v3 = xv[3*HW];
        const float* c = cent + cb * (KC * 4);
        float best = 3.4e38f, second = 3.4e38f; int bk = 0;
        #pragma unroll
        for (int k = 0; k < KC; k++) {
            float dot = smul(c[k*4+0], v0);
            dot = sadd(dot, smul(c[k*4+1], v1));
            dot = sadd(dot, smul(c[k*4+2], v2));
            dot = sadd(dot, smul(c[k*4+3], v3));
            float s = sadd(s_c2[cb*KC + k], smul(-2.f, dot));
            if (s < best) { second = best; best = s; bk = k; }
            else if (s < second) { second = s; }
        }
        if (second - best < 1e-3f * (1.f + fabsf(best)))
            bk = argmin_d4(c, v0, v1, v2, v3);
        s_idx[pr] = (unsigned char)bk;
    }
    __syncthreads();

    // LUT accumulate (Kahan-compensated: output feeds layer-2 argmin)
    const int oq    = tid & 63;
    const int plane = tid >> 6;         // 0..7 ; p = plane + 8*j
    float4 acc[4], cmp[4];
    #pragma unroll
    for (int j = 0; j < 4; j++) { acc[j] = make_float4(0.f,0.f,0.f,0.f);
                                  cmp[j] = make_float4(0.f,0.f,0.f,0.f); }

    for (int cb = 0; cb < NCB1; cb++) {
        const unsigned char* ib = s_idx + cb * 28;
        const float* lb = lut + (cb * KC) * CMID + (oq << 2);
        #pragma unroll
        for (int j = 0; j < 4; j++) {
            const int p = plane + (j << 3);
            if (p < 28) {
                float4 t = __ldg((const float4*)(lb + ((int)ib[p] << 8)));
                KAHAN(acc[j].x, cmp[j].x, t.x);
                KAHAN(acc[j].y, cmp[j].y, t.y);
                KAHAN(acc[j].z, cmp[j].z, t.z);
                KAHAN(acc[j].w, cmp[j].w, t.w);
            }
        }
    }

    const int o = oq << 2;
    const float4 sc = __ldg((const float4*)(scale + o));
    const float4 bi = __ldg((const float4*)(bias + o));
    float* ob = g_out1 + ((size_t)b * CMID + o) * HW + pt * 28;
    #pragma unroll
    for (int j = 0; j < 4; j++) {
        const int p = plane + (j << 3);
        if (p < 28) {
            float sx = ssub(acc[j].x, cmp[j].x), sy = ssub(acc[j].y, cmp[j].y);
            float sz = ssub(acc[j].z, cmp[j].z), sw = ssub(acc[j].w, cmp[j].w);
            ob[0*HW + p] = fmaxf(sadd(smul(sx, sc.x), bi.x), 0.f);
            ob[1*HW + p] = fmaxf(sadd(smul(sy, sc.y), bi.y), 0.f);
            ob[2*HW + p] = fmaxf(sadd(smul(sz, sc.z), bi.z), 0.f);
            ob[3*HW + p] = fmaxf(sadd(smul(sw, sc.w), bi.w), 0.f);
        }
    }
}

// ---------------------------------------------------------------------------
// Kernel 2: 3x3 AMM conv pad=1 (out1 -> out2[32,256,14,14]) + BN + ReLU
// ---------------------------------------------------------------------------
__global__ __launch_bounds__(512, 2) void k2_assign_accum(
    const float* __restrict__ cent, const float* __restrict__ lut,
    const float* __restrict__ scale, const float* __restrict__ bias)
{
    __shared__ float         s_c2[NCB2 * KC];
    __shared__ unsigned char s_idx[NCB2 * 28];

    const int b   = blockIdx.y;
    const int pt  = blockIdx.x;
    const int tid = threadIdx.x;

    for (int i = tid; i < NCB2 * KC; i += 512) {
        const float* c = cent + i * 9;
        float s = 0.f;
        #pragma unroll
        for (int d = 0; d < 9; d++) s = sadd(s, smul(c[d], c[d]));
        s_c2[i] = s;
    }
    __syncthreads();

    for (int pr = tid; pr < NCB2 * 28; pr += 512) {
        const int cb = pr / 28;
        const int p  = pr - cb * 28;
        const int pg = pt * 28 + p;
        const int y  = pg / 14;
        const int xx = pg - y * 14;
        const float* ib = g_out1 + ((size_t)b * CMID + cb) * HW;
        float v[9];
        #pragma unroll
        for (int dy = 0; dy < 3; dy++) {
            const int yy = y + dy - 1;
            #pragma unroll
            for (int dx = 0; dx < 3; dx++) {
                const int x2 = xx + dx - 1;
                v[dy*3+dx] = (yy >= 0 && yy < 14 && x2 >= 0 && x2 < 14)
                             ? ib[yy*14 + x2] : 0.f;
            }
        }
        const float* c = cent + cb * (KC * 9);
        float best = 3.4e38f, second = 3.4e38f; int bk = 0;
        #pragma unroll
        for (int k = 0; k < KC; k++) {
            float dot = 0.f;
            #pragma unroll
            for (int d = 0; d < 9; d++) dot = sadd(dot, smul(c[k*9+d], v[d]));
            float s = sadd(s_c2[cb*KC + k], smul(-2.f, dot));
            if (s < best) { second = best; best = s; bk = k; }
            else if (s < second) { second = s; }
        }
        if (second - best < 1e-3f * (1.f + fabsf(best)))
            bk = argmin_d9(c, v);
        s_idx[pr] = (unsigned char)bk;
    }
    __syncthreads();

    const int oq    = tid & 63;
    const int plane = tid >> 6;
    float4 acc[4], cmp[4];
    #pragma unroll
    for (int j = 0; j < 4; j++) { acc[j] = make_float4(0.f,0.f,0.f,0.f);
                                  cmp[j] = make_float4(0.f,0.f,0.f,0.f); }

    for (int cb = 0; cb < NCB2; cb++) {
        const unsigned char* ib = s_idx + cb * 28;
        const float* lb = lut + (cb * KC) * CMID + (oq << 2);
        #pragma unroll
        for (int j = 0; j < 4; j++) {
            const int p = plane + (j << 3);
            if (p < 28) {
                float4 t = __ldg((const float4*)(lb + ((int)ib[p] << 8)));
                KAHAN(acc[j].x, cmp[j].x, t.x);
                KAHAN(acc[j].y, cmp[j].y, t.y);
                KAHAN(acc[j].z, cmp[j].z, t.z);
                KAHAN(acc[j].w, cmp[j].w, t.w);
            }
        }
    }

    const int o = oq << 2;
    const float4 sc = __ldg((const float4*)(scale + o));
    const float4 bi = __ldg((const float4*)(bias + o));
    float* ob = g_out2 + ((size_t)b * CMID + o) * HW + pt * 28;
    #pragma unroll
    for (int j = 0; j < 4; j++) {
        const int p = plane + (j << 3);
        if (p < 28) {
            float sx = ssub(acc[j].x, cmp[j].x), sy = ssub(acc[j].y, cmp[j].y);
            float sz = ssub(acc[j].z, cmp[j].z), sw = ssub(acc[j].w, cmp[j].w);
            ob[0*HW + p] = fmaxf(sadd(smul(sx, sc.x), bi.x), 0.f);
            ob[1*HW + p] = fmaxf(sadd(smul(sy, sc.y), bi.y), 0.f);
            ob[2*HW + p] = fmaxf(sadd(smul(sz, sc.z), bi.z), 0.f);
            ob[3*HW + p] = fmaxf(sadd(smul(sw, sc.w), bi.w), 0.f);
        }
    }
}

// ---------------------------------------------------------------------------
// Kernel 3: 1x1 AMM conv (out2 -> 1024) + BN + residual add + ReLU -> d_out
// Final layer: plain fp32 accumulation (output tolerance 1e-3, no downstream)
// ---------------------------------------------------------------------------
__global__ __launch_bounds__(512, 2) void k3_assign_accum(
    const float* __restrict__ x, const float* __restrict__ cent,
    const float* __restrict__ lut, const float* __restrict__ scale,
    const float* __restrict__ bias, float* __restrict__ out)
{
    __shared__ float         s_c2[NCB3 * KC];   // 4 KB
    __shared__ unsigned char s_idx[NCB3 * 7];   // [g][p]

    const int b   = blockIdx.y;
    const int pt  = blockIdx.x;    // 0..27, 7 positions each
    const int tid = threadIdx.x;

    for (int i = tid; i < NCB3 * KC; i += 512) {
        const float* c = cent + i * 4;
        float s = 0.f;
        #pragma unroll
        for (int d = 0; d < 4; d++) s = sadd(s, smul(c[d], c[d]));
        s_c2[i] = s;
    }
    __syncthreads();

    if (tid < NCB3 * 7) {
        const int g = tid / 7;
        const int p = tid - g * 7;
        const int pg = pt * 7 + p;
        const float* iv = g_out2 + ((size_t)b * CMID + g * 4) * HW + pg;
        const float v0 = iv[0], v1 = iv[HW], v2 = iv[2*HW], v3 = iv[3*HW];
        const float* c = cent + g * (KC * 4);
        float best = 3.4e38f, second = 3.4e38f; int bk = 0;
        #pragma unroll
        for (int k = 0; k < KC; k++) {
            float dot = smul(c[k*4+0], v0);
            dot = sadd(dot, smul(c[k*4+1], v1));
            dot = sadd(dot, smul(c[k*4+2], v2));
            dot = sadd(dot, smul(c[k*4+3], v3));
            float s = sadd(s_c2[g*KC + k], smul(-2.f, dot));
            if (s < best) { second = best; best = s; bk = k; }
            else if (s < second) { second = s; }
        }
        if (second - best < 1e-3f * (1.f + fabsf(best)))
            bk = argmin_d4(c, v0, v1, v2, v3);
        s_idx[tid] = (unsigned char)bk;
    }
    __syncthreads();

    const int oq    = tid & 255;       // o = oq*4 in [0,1024)
    const int plane = tid >> 8;        // 0..1 ; p = plane + 2*j
    float4 acc[4];
    #pragma unroll
    for (int j = 0; j < 4; j++) acc[j] = make_float4(0.f, 0.f, 0.f, 0.f);

    for (int g = 0; g < NCB3; g++) {
        const unsigned char* ib = s_idx + g * 7;
        const float* lb = lut + (g * KC) * COUT + (oq << 2);
        #pragma unroll
        for (int j = 0; j < 4; j++) {
            const int p = plane + (j << 1);
            if (p < 7) {
                float4 t = __ldg((const float4*)(lb + ((int)ib[p] << 10)));
                acc[j].x = sadd(acc[j].x, t.x); acc[j].y = sadd(acc[j].y, t.y);
                acc[j].z = sadd(acc[j].z, t.z); acc[j].w = sadd(acc[j].w, t.w);
            }
        }
    }

    const int o = oq << 2;
    const float4 sc = __ldg((const float4*)(scale + o));
    const float4 bi = __ldg((const float4*)(bias + o));
    const float* xb = x   + ((size_t)b * COUT + o) * HW + pt * 7;
    float*       ob = out + ((size_t)b * COUT + o) * HW + pt * 7;
    #pragma unroll
    for (int j = 0; j < 4; j++) {
        const int p = plane + (j << 1);
        if (p < 7) {
            ob[0*HW + p] = fmaxf(sadd(sadd(smul(acc[j].x, sc.x), bi.x), xb[0*HW + p]), 0.f);
            ob[1*HW + p] = fmaxf(sadd(sadd(smul(acc[j].y, sc.y), bi.y), xb[1*HW + p]), 0.f);
            ob[2*HW + p] = fmaxf(sadd(sadd(smul(acc[j].z, sc.z), bi.z), xb[2*HW + p]), 0.f);
            ob[3*HW + p] = fmaxf(sadd(sadd(smul(acc[j].w, sc.w), bi.w), xb[3*HW + p]), 0.f);
        }
    }
}

// ---------------------------------------------------------------------------
extern "C" void kernel_launch(void* const* d_in, const int* in_sizes, int n_in,
                              void* d_out, int out_size)
{
    const float* x      = (const float*)d_in[0];
    const float* c1c    = (const float*)d_in[1];
    const float* c1lut  = (const float*)d_in[2];
    const float* c1s    = (const float*)d_in[3];
    const float* c1b    = (const float*)d_in[4];
    const float* c2c    = (const float*)d_in[5];
    const float* c2lut  = (const float*)d_in[6];
    const float* c2s    = (const float*)d_in[7];
    const float* c2b    = (const float*)d_in[8];
    const float* c3c    = (const float*)d_in[9];
    const float* c3lut  = (const float*)d_in[10];
    const float* c3s    = (const float*)d_in[11];
    const float* c3b    = (const float*)d_in[12];
    float* out = (float*)d_out;

    dim3 g12(7, BATCH);
    dim3 g3(28, BATCH);
    k1_assign_accum<<<g12, 512>>>(x, c1c, c1lut, c1s, c1b);
    k2_assign_accum<<<g12, 512>>>(c2c, c2lut, c2s, c2b);
    k3_assign_accum<<<g3, 512>>>(x, c3c, c3lut, c3s, c3b, out);
}

// round 17
// speedup vs baseline: 1.2036x; 1.2036x over previous
#include <cuda_runtime.h>
#include <stdint.h>

#define BATCH 32
#define HW    196        // 14x14
#define CIN   1024
#define CMID  256
#define COUT  1024
#define NCB1  256        // 1024/4
#define NCB2  256        // one codebook per channel (dsub=9)
#define NCB3  64         // 256/4
#define KC    16

// Scratch (no runtime allocation allowed)
__device__ float g_out1[BATCH * CMID * HW];
__device__ float g_out2[BATCH * CMID * HW];

__device__ __forceinline__ float smul(float a, float b) { return __fmul_rn(a, b); }
__device__ __forceinline__ float sadd(float a, float b) { return __fadd_rn(a, b); }
__device__ __forceinline__ float ssub(float a, float b) { return __fsub_rn(a, b); }

// Kahan step: acc += t with compensation
#define KAHAN(s, comp, t) do {                         \
    float _y  = ssub((t), (comp));                     \
    float _tt = sadd((s), _y);                         \
    (comp) = ssub(ssub(_tt, (s)), _y);                 \
    (s) = _tt;                                         \
} while (0)

#define KAHAN4(a, c, t) do {                           \
    KAHAN((a).x, (c).x, (t).x);                        \
    KAHAN((a).y, (c).y, (t).y);                        \
    KAHAN((a).z, (c).z, (t).z);                        \
    KAHAN((a).w, (c).w, (t).w);                        \
} while (0)

// ---------------------------------------------------------------------------
// fp64 argmin fallback for near-ties (matches the fp64 reference exactly)
// ---------------------------------------------------------------------------
__device__ __noinline__ int argmin_d4(const float* __restrict__ c,
                                      float v0, float v1, float v2, float v3)
{
    double bv = 1e300; int bk = 0;
    for (int k = 0; k < KC; k++) {
        const float* ck = c + k * 4;
        double c2 = (double)ck[0]*ck[0] + (double)ck[1]*ck[1]
                  + (double)ck[2]*ck[2] + (double)ck[3]*ck[3];
        double dot = (double)ck[0]*v0 + (double)ck[1]*v1
                   + (double)ck[2]*v2 + (double)ck[3]*v3;
        double s = c2 - 2.0 * dot;
        if (s < bv) { bv = s; bk = k; }
    }
    return bk;
}

__device__ __noinline__ int argmin_d9(const float* __restrict__ c,
                                      const float* __restrict__ v)
{
    double bv = 1e300; int bk = 0;
    for (int k = 0; k < KC; k++) {
        const float* ck = c + k * 9;
        double c2 = 0.0, dot = 0.0;
        for (int d = 0; d < 9; d++) {
            c2  += (double)ck[d] * ck[d];
            dot += (double)ck[d] * v[d];
        }
        double s = c2 - 2.0 * dot;
        if (s < bv) { bv = s; bk = k; }
    }
    return bk;
}

// ---------------------------------------------------------------------------
// Kernel 1: 1x1 AMM conv  (x[32,1024,14,14] -> out1[32,256,14,14]) + BN + ReLU
// grid (14, 32): 14 positions per block. 448 threads (7 planes x 64 o-quads).
// ---------------------------------------------------------------------------
__global__ __launch_bounds__(448, 2) void k1_assign_accum(
    const float* __restrict__ x, const float* __restrict__ cent,
    const float* __restrict__ lut, const float* __restrict__ scale,
    const float* __restrict__ bias)
{
    __shared__ float         s_c2[NCB1 * KC];      // 16 KB
    __shared__ unsigned char s_idx[NCB1 * 14];     // [cb][p]

    const int b   = blockIdx.y;
    const int pt  = blockIdx.x;      // 0..13, 14 positions each
    const int tid = threadIdx.x;

    for (int i = tid; i < NCB1 * KC; i += 448) {
        const float* c = cent + i * 4;
        float s = 0.f;
        #pragma unroll
        for (int d = 0; d < 4; d++) s = sadd(s, smul(c[d], c[d]));
        s_c2[i] = s;
    }
    __syncthreads();

    const float* xb = x + (size_t)b * CIN * HW;
    for (int pr = tid; pr < NCB1 * 14; pr += 448) {
        const int cb = pr / 14;
        const int p  = pr - cb * 14;
        const int pg = pt * 14 + p;
        const float* xv = xb + (cb * 4) * HW + pg;
        const float v0 = xv[0], v1 = xv[HW], v2 = xv[2*HW], v3 = xv[3*HW];
        const float* c = cent + cb * (KC * 4);
        float best = 3.4e38f, second = 3.4e38f; int bk = 0;
        #pragma unroll
        for (int k = 0; k < KC; k++) {
            float dot = smul(c[k*4+0], v0);
            dot = sadd(dot, smul(c[k*4+1], v1));
            dot = sadd(dot, smul(c[k*4+2], v2));
            dot = sadd(dot, smul(c[k*4+3], v3));
            float s = sadd(s_c2[cb*KC + k], smul(-2.f, dot));
            if (s < best) { second = best; best = s; bk = k; }
            else if (s < second) { second = s; }
        }
        if (second - best < 1e-3f * (1.f + fabsf(best)))
            bk = argmin_d4(c, v0, v1, v2, v3);
        s_idx[pr] = (unsigned char)bk;
    }
    __syncthreads();

    // LUT accumulate (Kahan; cb-ascending order preserved). p0=plane, p1=plane+7.
    const int oq    = tid & 63;
    const int plane = tid >> 6;      // 0..6
    const int p0 = plane, p1 = plane + 7;
    float4 a0 = make_float4(0.f,0.f,0.f,0.f), c0 = a0;
    float4 a1 = a0, c1 = a0;

    for (int cb = 0; cb < NCB1; cb += 2) {
        const unsigned char* ib0 = s_idx + cb * 14;
        const float* lb0 = lut + (cb * KC) * CMID + (oq << 2);
        const float* lb1 = lb0 + KC * CMID;
        float4 t00 = __ldg((const float4*)(lb0 + ((int)ib0[p0]      << 8)));
        float4 t01 = __ldg((const float4*)(lb0 + ((int)ib0[p1]      << 8)));
        float4 t10 = __ldg((const float4*)(lb1 + ((int)ib0[14 + p0] << 8)));
        float4 t11 = __ldg((const float4*)(lb1 + ((int)ib0[14 + p1] << 8)));
        KAHAN4(a0, c0, t00);
        KAHAN4(a1, c1, t01);
        KAHAN4(a0, c0, t10);
        KAHAN4(a1, c1, t11);
    }

    const int o = oq << 2;
    const float4 sc = __ldg((const float4*)(scale + o));
    const float4 bi = __ldg((const float4*)(bias + o));
    float* ob = g_out1 + ((size_t)b * CMID + o) * HW + pt * 14;
    float s0x = ssub(a0.x, c0.x), s0y = ssub(a0.y, c0.y);
    float s0z = ssub(a0.z, c0.z), s0w = ssub(a0.w, c0.w);
    float s1x = ssub(a1.x, c1.x), s1y = ssub(a1.y, c1.y);
    float s1z = ssub(a1.z, c1.z), s1w = ssub(a1.w, c1.w);
    ob[0*HW + p0] = fmaxf(sadd(smul(s0x, sc.x), bi.x), 0.f);
    ob[1*HW + p0] = fmaxf(sadd(smul(s0y, sc.y), bi.y), 0.f);
    ob[2*HW + p0] = fmaxf(sadd(smul(s0z, sc.z), bi.z), 0.f);
    ob[3*HW + p0] = fmaxf(sadd(smul(s0w, sc.w), bi.w), 0.f);
    ob[0*HW + p1] = fmaxf(sadd(smul(s1x, sc.x), bi.x), 0.f);
    ob[1*HW + p1] = fmaxf(sadd(smul(s1y, sc.y), bi.y), 0.f);
    ob[2*HW + p1] = fmaxf(sadd(smul(s1z, sc.z), bi.z), 0.f);
    ob[3*HW + p1] = fmaxf(sadd(smul(s1w, sc.w), bi.w), 0.f);
}

// ---------------------------------------------------------------------------
// Kernel 2: 3x3 AMM conv pad=1 (out1 -> out2[32,256,14,14]) + BN + ReLU
// grid (14, 32), 448 threads.
// ---------------------------------------------------------------------------
__global__ __launch_bounds__(448, 2) void k2_assign_accum(
    const float* __restrict__ cent, const float* __restrict__ lut,
    const float* __restrict__ scale, const float* __restrict__ bias)
{
    __shared__ float         s_c2[NCB2 * KC];
    __shared__ unsigned char s_idx[NCB2 * 14];

    const int b   = blockIdx.y;
    const int pt  = blockIdx.x;
    const int tid = threadIdx.x;

    for (int i = tid; i < NCB2 * KC; i += 448) {
        const float* c = cent + i * 9;
        float s = 0.f;
        #pragma unroll
        for (int d = 0; d < 9; d++) s = sadd(s, smul(c[d], c[d]));
        s_c2[i] = s;
    }
    __syncthreads();

    for (int pr = tid; pr < NCB2 * 14; pr += 448) {
        const int cb = pr / 14;
        const int p  = pr - cb * 14;
        const int pg = pt * 14 + p;
        const int y  = pg / 14;
        const int xx = pg - y * 14;
        const float* ib = g_out1 + ((size_t)b * CMID + cb) * HW;
        float v[9];
        #pragma unroll
        for (int dy = 0; dy < 3; dy++) {
            const int yy = y + dy - 1;
            #pragma unroll
            for (int dx = 0; dx < 3; dx++) {
                const int x2 = xx + dx - 1;
                v[dy*3+dx] = (yy >= 0 && yy < 14 && x2 >= 0 && x2 < 14)
                             ? ib[yy*14 + x2] : 0.f;
            }
        }
        const float* c = cent + cb * (KC * 9);
        float best = 3.4e38f, second = 3.4e38f; int bk = 0;
        #pragma unroll
        for (int k = 0; k < KC; k++) {
            float dot = 0.f;
            #pragma unroll
            for (int d = 0; d < 9; d++) dot = sadd(dot, smul(c[k*9+d], v[d]));
            float s = sadd(s_c2[cb*KC + k], smul(-2.f, dot));
            if (s < best) { second = best; best = s; bk = k; }
            else if (s < second) { second = s; }
        }
        if (second - best < 1e-3f * (1.f + fabsf(best)))
            bk = argmin_d9(c, v);
        s_idx[pr] = (unsigned char)bk;
    }
    __syncthreads();

    const int oq    = tid & 63;
    const int plane = tid >> 6;
    const int p0 = plane, p1 = plane + 7;
    float4 a0 = make_float4(0.f,0.f,0.f,0.f), c0 = a0;
    float4 a1 = a0, c1 = a0;

    for (int cb = 0; cb < NCB2; cb += 2) {
        const unsigned char* ib0 = s_idx + cb * 14;
        const float* lb0 = lut + (cb * KC) * CMID + (oq << 2);
        const float* lb1 = lb0 + KC * CMID;
        float4 t00 = __ldg((const float4*)(lb0 + ((int)ib0[p0]      << 8)));
        float4 t01 = __ldg((const float4*)(lb0 + ((int)ib0[p1]      << 8)));
        float4 t10 = __ldg((const float4*)(lb1 + ((int)ib0[14 + p0] << 8)));
        float4 t11 = __ldg((const float4*)(lb1 + ((int)ib0[14 + p1] << 8)));
        KAHAN4(a0, c0, t00);
        KAHAN4(a1, c1, t01);
        KAHAN4(a0, c0, t10);
        KAHAN4(a1, c1, t11);
    }

    const int o = oq << 2;
    const float4 sc = __ldg((const float4*)(scale + o));
    const float4 bi = __ldg((const float4*)(bias + o));
    float* ob = g_out2 + ((size_t)b * CMID + o) * HW + pt * 14;
    float s0x = ssub(a0.x, c0.x), s0y = ssub(a0.y, c0.y);
    float s0z = ssub(a0.z, c0.z), s0w = ssub(a0.w, c0.w);
    float s1x = ssub(a1.x, c1.x), s1y = ssub(a1.y, c1.y);
    float s1z = ssub(a1.z, c1.z), s1w = ssub(a1.w, c1.w);
    ob[0*HW + p0] = fmaxf(sadd(smul(s0x, sc.x), bi.x), 0.f);
    ob[1*HW + p0] = fmaxf(sadd(smul(s0y, sc.y), bi.y), 0.f);
    ob[2*HW + p0] = fmaxf(sadd(smul(s0z, sc.z), bi.z), 0.f);
    ob[3*HW + p0] = fmaxf(sadd(smul(s0w, sc.w), bi.w), 0.f);
    ob[0*HW + p1] = fmaxf(sadd(smul(s1x, sc.x), bi.x), 0.f);
    ob[1*HW + p1] = fmaxf(sadd(smul(s1y, sc.y), bi.y), 0.f);
    ob[2*HW + p1] = fmaxf(sadd(smul(s1z, sc.z), bi.z), 0.f);
    ob[3*HW + p1] = fmaxf(sadd(smul(s1w, sc.w), bi.w), 0.f);
}

// ---------------------------------------------------------------------------
// Kernel 3: 1x1 AMM conv (out2 -> 1024) + BN + residual add + ReLU -> d_out
// Final layer: plain fp32 accumulation (output tolerance 1e-3, no downstream)
// ---------------------------------------------------------------------------
__global__ __launch_bounds__(512, 2) void k3_assign_accum(
    const float* __restrict__ x, const float* __restrict__ cent,
    const float* __restrict__ lut, const float* __restrict__ scale,
    const float* __restrict__ bias, float* __restrict__ out)
{
    __shared__ float         s_c2[NCB3 * KC];   // 4 KB
    __shared__ unsigned char s_idx[NCB3 * 7];   // [g][p]

    const int b   = blockIdx.y;
    const int pt  = blockIdx.x;    // 0..27, 7 positions each
    const int tid = threadIdx.x;

    for (int i = tid; i < NCB3 * KC; i += 512) {
        const float* c = cent + i * 4;
        float s = 0.f;
        #pragma unroll
        for (int d = 0; d < 4; d++) s = sadd(s, smul(c[d], c[d]));
        s_c2[i] = s;
    }
    __syncthreads();

    if (tid < NCB3 * 7) {
        const int g = tid / 7;
        const int p = tid - g * 7;
        const int pg = pt * 7 + p;
        const float* iv = g_out2 + ((size_t)b * CMID + g * 4) * HW + pg;
        const float v0 = iv[0], v1 = iv[HW], v2 = iv[2*HW], v3 = iv[3*HW];
        const float* c = cent + g * (KC * 4);
        float best = 3.4e38f, second = 3.4e38f; int bk = 0;
        #pragma unroll
        for (int k = 0; k < KC; k++) {
            float dot = smul(c[k*4+0], v0);
            dot = sadd(dot, smul(c[k*4+1], v1));
            dot = sadd(dot, smul(c[k*4+2], v2));
            dot = sadd(dot, smul(c[k*4+3], v3));
            float s = sadd(s_c2[g*KC + k], smul(-2.f, dot));
            if (s < best) { second = best; best = s; bk = k; }
            else if (s < second) { second = s; }
        }
        if (second - best < 1e-3f * (1.f + fabsf(best)))
            bk = argmin_d4(c, v0, v1, v2, v3);
        s_idx[tid] = (unsigned char)bk;
    }
    __syncthreads();

    const int oq    = tid & 255;       // o = oq*4 in [0,1024)
    const int plane = tid >> 8;        // 0..1 ; p = plane + 2*j
    float4 acc[4];
    #pragma unroll
    for (int j = 0; j < 4; j++) acc[j] = make_float4(0.f, 0.f, 0.f, 0.f);

    #pragma unroll 2
    for (int g = 0; g < NCB3; g++) {
        const unsigned char* ib = s_idx + g * 7;
        const float* lb = lut + (g * KC) * COUT + (oq << 2);
        #pragma unroll
        for (int j = 0; j < 4; j++) {
            const int p = plane + (j << 1);
            if (p < 7) {
                float4 t = __ldg((const float4*)(lb + ((int)ib[p] << 10)));
                acc[j].x = sadd(acc[j].x, t.x); acc[j].y = sadd(acc[j].y, t.y);
                acc[j].z = sadd(acc[j].z, t.z); acc[j].w = sadd(acc[j].w, t.w);
            }
        }
    }

    const int o = oq << 2;
    const float4 sc = __ldg((const float4*)(scale + o));
    const float4 bi = __ldg((const float4*)(bias + o));
    const float* xb = x   + ((size_t)b * COUT + o) * HW + pt * 7;
    float*       ob = out + ((size_t)b * COUT + o) * HW + pt * 7;
    #pragma unroll
    for (int j = 0; j < 4; j++) {
        const int p = plane + (j << 1);
        if (p < 7) {
            ob[0*HW + p] = fmaxf(sadd(sadd(smul(acc[j].x, sc.x), bi.x), xb[0*HW + p]), 0.f);
            ob[1*HW + p] = fmaxf(sadd(sadd(smul(acc[j].y, sc.y), bi.y), xb[1*HW + p]), 0.f);
            ob[2*HW + p] = fmaxf(sadd(sadd(smul(acc[j].z, sc.z), bi.z), xb[2*HW + p]), 0.f);
            ob[3*HW + p] = fmaxf(sadd(sadd(smul(acc[j].w, sc.w), bi.w), xb[3*HW + p]), 0.f);
        }
    }
}

// ---------------------------------------------------------------------------
extern "C" void kernel_launch(void* const* d_in, const int* in_sizes, int n_in,
                              void* d_out, int out_size)
{
    const float* x      = (const float*)d_in[0];
    const float* c1c    = (const float*)d_in[1];
    const float* c1lut  = (const float*)d_in[2];
    const float* c1s    = (const float*)d_in[3];
    const float* c1b    = (const float*)d_in[4];
    const float* c2c    = (const float*)d_in[5];
    const float* c2lut  = (const float*)d_in[6];
    const float* c2s    = (const float*)d_in[7];
    const float* c2b    = (const float*)d_in[8];
    const float* c3c    = (const float*)d_in[9];
    const float* c3lut  = (const float*)d_in[10];
    const float* c3s    = (const float*)d_in[11];
    const float* c3b    = (const float*)d_in[12];
    float* out = (float*)d_out;

    dim3 g12(14, BATCH);
    dim3 g3(28, BATCH);
    k1_assign_accum<<<g12, 448>>>(x, c1c, c1lut, c1s, c1b);
    k2_assign_accum<<<g12, 448>>>(c2c, c2lut, c2s, c2b);
    k3_assign_accum<<<g3, 512>>>(x, c3c, c3lut, c3s, c3b, out);
}